// round 1
// baseline (speedup 1.0000x reference)
#include <cuda_runtime.h>
#include <cstdint>

#define N_Q   50000
#define M_S   50000
#define KNNB  32
#define KPN   15
#define CIN   64
#define COUT  128
#define KDIM  (KPN * CIN)      // 960
#define KP_EXT_INV (1.0f / 1.2f)

#define GBM   128
#define M_PAD (391 * GBM)      // 50048 >= 50000

// Scratch: kernel_feats flattened [n][e*64+c], zero-initialized device globals.
__device__ float g_kf[(size_t)M_PAD * KDIM];
__device__ float g_inv[M_PAD];

// ---------------------------------------------------------------------------
// Kernel 1: gather neighbors, kernel-point influence, aggregate to g_kf,
// and compute 1/max(valid_count,1) per query.
// 256 threads = 4 queries x 64 threads (thread <-> channel c).
// ---------------------------------------------------------------------------
__global__ __launch_bounds__(256) void k1_gather(
    const float* __restrict__ q_pts, const float* __restrict__ s_pts,
    const float* __restrict__ s_feats, const int* __restrict__ nidx,
    const float* __restrict__ kpts)
{
    __shared__ float kp_s[KPN * 3];
    __shared__ float relp_s[4][KNNB][3];
    __shared__ int   idx_s[4][KNNB];
    __shared__ float h_s[4][KNNB][KPN];
    __shared__ float rsum_s[4][2][KNNB];

    const int tid   = threadIdx.x;
    const int q     = tid >> 6;        // 0..3 query slot
    const int qlane = tid & 63;        // 0..63 channel
    const int lane  = tid & 31;
    const int winq  = (tid >> 5) & 1;  // warp within query group
    const int qid   = blockIdx.x * 4 + q;   // grid sized exactly: 12500*4=50000

    if (tid < KPN * 3) kp_s[tid] = kpts[tid];

    // indices + relative positions: threads 0..127 cover 4 queries x 32 nbrs
    if (tid < 128) {
        int qq = tid >> 5, nb = tid & 31;
        int gq = blockIdx.x * 4 + qq;
        int id = nidx[gq * KNNB + nb];
        idx_s[qq][nb] = id;
        float px, py, pz;
        if (id < M_S) {
            px = s_pts[id * 3 + 0];
            py = s_pts[id * 3 + 1];
            pz = s_pts[id * 3 + 2];
        } else {
            px = py = pz = 1e6f;   // shadow point
        }
        relp_s[qq][nb][0] = px - q_pts[gq * 3 + 0];
        relp_s[qq][nb][1] = py - q_pts[gq * 3 + 1];
        relp_s[qq][nb][2] = pz - q_pts[gq * 3 + 2];
    }
    __syncthreads();

    // h[nb][e] = max(0, 1 - sqrt(|rel - kp|^2 + 1e-8)/1.2); 480 values / 64 thr
    #pragma unroll
    for (int t = 0; t < 8; t++) {
        int j = t * 64 + qlane;
        if (j < KNNB * KPN) {
            int nb = j / KPN;
            int e  = j - nb * KPN;
            float dx = relp_s[q][nb][0] - kp_s[e * 3 + 0];
            float dy = relp_s[q][nb][1] - kp_s[e * 3 + 1];
            float dz = relp_s[q][nb][2] - kp_s[e * 3 + 2];
            float d2 = fmaf(dx, dx, fmaf(dy, dy, fmaf(dz, dz, 1e-8f)));
            float h  = 1.0f - sqrtf(d2) * KP_EXT_INV;
            h_s[q][nb][e] = fmaxf(h, 0.0f);
        }
    }
    __syncthreads();

    const int c = qlane;
    float acc[KPN];
    #pragma unroll
    for (int e = 0; e < KPN; e++) acc[e] = 0.0f;

    #pragma unroll 4
    for (int nb = 0; nb < KNNB; nb++) {
        int id = idx_s[q][nb];
        float f = 0.0f;
        if (id < M_S) f = __ldg(&s_feats[(size_t)id * CIN + c]);
        // row sum (for validity test) via warp butterfly
        float rs = f;
        #pragma unroll
        for (int off = 16; off; off >>= 1)
            rs += __shfl_xor_sync(0xffffffffu, rs, off);
        if (lane == 0) rsum_s[q][winq][nb] = rs;
        #pragma unroll
        for (int e = 0; e < KPN; e++)
            acc[e] = fmaf(h_s[q][nb][e], f, acc[e]);
    }
    __syncthreads();

    // valid-neighbor count (warp 0 of each query group: qlane 0..31)
    if (qlane < KNNB) {
        float tot = rsum_s[q][0][qlane] + rsum_s[q][1][qlane];
        unsigned int bal = __ballot_sync(0xffffffffu, tot > 0.0f);
        if (qlane == 0) {
            int cnt = __popc(bal);
            g_inv[qid] = 1.0f / (float)(cnt > 0 ? cnt : 1);
        }
    }

    float* dst = &g_kf[(size_t)qid * KDIM];
    #pragma unroll
    for (int e = 0; e < KPN; e++)
        dst[e * CIN + c] = acc[e];
}

// ---------------------------------------------------------------------------
// Kernel 2: C[50048,128] = A[50048,960] @ B[960,128], scaled per-row by g_inv.
// 128x128x16 tile, 256 threads, 8x8 microtile, packed fma.rn.f32x2.
// ---------------------------------------------------------------------------
#define GBN 128
#define GBK 16

__global__ __launch_bounds__(256) void k2_gemm(
    const float* __restrict__ W, float* __restrict__ out)
{
    __shared__ float As[GBK][GBM + 4];   // k-major A (transposed on load)
    __shared__ float Bs[GBK][GBN + 4];

    const int tid = threadIdx.x;
    const int tx  = tid & 15;
    const int ty  = tid >> 4;
    const int m0  = blockIdx.x * GBM;

    const float* A = g_kf;

    unsigned long long cc[8][4];
    #pragma unroll
    for (int i = 0; i < 8; i++)
        #pragma unroll
        for (int j = 0; j < 4; j++) cc[i][j] = 0ull;

    const int arow  = tid >> 2;       // 0..63
    const int acol4 = (tid & 3) * 4;  // 0,4,8,12

    for (int k0 = 0; k0 < KDIM; k0 += GBK) {
        // A tile: load float4 along k, scatter into k-major smem
        #pragma unroll
        for (int it = 0; it < 2; it++) {
            int m = arow + it * 64;
            float4 v = *(const float4*)&A[(size_t)(m0 + m) * KDIM + k0 + acol4];
            As[acol4 + 0][m] = v.x;
            As[acol4 + 1][m] = v.y;
            As[acol4 + 2][m] = v.z;
            As[acol4 + 3][m] = v.w;
        }
        // B tile: contiguous
        #pragma unroll
        for (int it = 0; it < 2; it++) {
            int idx4 = tid + it * 256;       // 0..511
            int k  = idx4 >> 5;
            int n4 = (idx4 & 31) * 4;
            *(float4*)&Bs[k][n4] = *(const float4*)&W[(k0 + k) * COUT + n4];
        }
        __syncthreads();

        #pragma unroll
        for (int kk = 0; kk < GBK; kk++) {
            float a[8], b[8];
            *(float4*)&a[0] = *(const float4*)&As[kk][ty * 8 + 0];
            *(float4*)&a[4] = *(const float4*)&As[kk][ty * 8 + 4];
            *(float4*)&b[0] = *(const float4*)&Bs[kk][tx * 8 + 0];
            *(float4*)&b[4] = *(const float4*)&Bs[kk][tx * 8 + 4];
            unsigned long long b2[4];
            #pragma unroll
            for (int j = 0; j < 4; j++)
                asm("mov.b64 %0, {%1, %2};" : "=l"(b2[j]) : "f"(b[2*j]), "f"(b[2*j+1]));
            #pragma unroll
            for (int i = 0; i < 8; i++) {
                unsigned long long a2;
                asm("mov.b64 %0, {%1, %1};" : "=l"(a2) : "f"(a[i]));
                #pragma unroll
                for (int j = 0; j < 4; j++)
                    asm("fma.rn.f32x2 %0, %1, %2, %0;"
                        : "+l"(cc[i][j]) : "l"(a2), "l"(b2[j]));
            }
        }
        __syncthreads();
    }

    #pragma unroll
    for (int i = 0; i < 8; i++) {
        int m = m0 + ty * 8 + i;
        if (m < N_Q) {
            float inv = g_inv[m];
            float o[8];
            #pragma unroll
            for (int j = 0; j < 4; j++) {
                float lo, hi;
                asm("mov.b64 {%0, %1}, %2;" : "=f"(lo), "=f"(hi) : "l"(cc[i][j]));
                o[2*j]   = lo * inv;
                o[2*j+1] = hi * inv;
            }
            *(float4*)&out[(size_t)m * COUT + tx * 8 + 0] = make_float4(o[0], o[1], o[2], o[3]);
            *(float4*)&out[(size_t)m * COUT + tx * 8 + 4] = make_float4(o[4], o[5], o[6], o[7]);
        }
    }
}

// ---------------------------------------------------------------------------
extern "C" void kernel_launch(void* const* d_in, const int* in_sizes, int n_in,
                              void* d_out, int out_size)
{
    const float* q_pts   = (const float*)d_in[0];
    const float* s_pts   = (const float*)d_in[1];
    const float* s_feats = (const float*)d_in[2];
    const int*   nidx    = (const int*)  d_in[3];
    const float* W       = (const float*)d_in[4];
    const float* kpts    = (const float*)d_in[5];
    float* out = (float*)d_out;

    k1_gather<<<N_Q / 4, 256>>>(q_pts, s_pts, s_feats, nidx, kpts);
    k2_gemm<<<M_PAD / GBM, 256>>>(W, out);
}

// round 2
// speedup vs baseline: 1.8897x; 1.8897x over previous
#include <cuda_runtime.h>
#include <cstdint>

#define N_Q   50000
#define M_S   50000
#define KNNB  32
#define KPN   15
#define CIN   64
#define COUT  128
#define KDIM  (KPN * CIN)      // 960
#define KP_EXT_INV (1.0f / 1.2f)

#define BM   128
#define BN   128
#define BK   32
#define ASTR 36                // 32 + 4 pad (keeps 16B align, kills conflicts)
#define BSTR 132               // 128 + 4 pad
#define ASZ  (BM * ASTR)
#define BSZ  (BK * BSTR)
#define NKC  (KDIM / BK)       // 30
#define M_PAD (391 * BM)       // 50048

// Scratch (device globals are zero-initialized; padding rows never written)
__device__ float g_kf[(size_t)M_PAD * KDIM];   // tf32 bits
__device__ float g_wt[KDIM * COUT];            // tf32 bits of W
__device__ float g_inv[M_PAD];
__device__ float g_rs[M_S];                    // per-support-row channel sum

// ---------------------------------------------------------------------------
// k0a: rowsum of s_feats per support point (for validity test)
// warp per row, lane handles 2 channels.
// ---------------------------------------------------------------------------
__global__ __launch_bounds__(256) void k0a_rowsum(const float* __restrict__ sf)
{
    int wid = threadIdx.x >> 5, lane = threadIdx.x & 31;
    int row = blockIdx.x * 8 + wid;
    float2 v = *(const float2*)&sf[(size_t)row * CIN + lane * 2];
    float s = v.x + v.y;
    #pragma unroll
    for (int off = 16; off; off >>= 1) s += __shfl_xor_sync(0xffffffffu, s, off);
    if (lane == 0) g_rs[row] = s;
}

// ---------------------------------------------------------------------------
// k0b: convert W to tf32 (rna rounding)
// ---------------------------------------------------------------------------
__global__ __launch_bounds__(256) void k0b_cvtw(const float* __restrict__ W)
{
    int i = (blockIdx.x * 256 + threadIdx.x) * 4;   // grid covers exactly
    float4 v = *(const float4*)&W[i];
    uint4 o;
    asm("cvt.rna.tf32.f32 %0, %1;" : "=r"(o.x) : "f"(v.x));
    asm("cvt.rna.tf32.f32 %0, %1;" : "=r"(o.y) : "f"(v.y));
    asm("cvt.rna.tf32.f32 %0, %1;" : "=r"(o.z) : "f"(v.z));
    asm("cvt.rna.tf32.f32 %0, %1;" : "=r"(o.w) : "f"(v.w));
    *reinterpret_cast<uint4*>(&g_wt[i]) = o;
}

// ---------------------------------------------------------------------------
// k1: gather + kernel-point aggregation.  Warp per query, lane = 2 channels.
// ---------------------------------------------------------------------------
__global__ __launch_bounds__(256) void k1_gather(
    const float* __restrict__ q_pts, const float* __restrict__ s_pts,
    const float* __restrict__ s_feats, const int* __restrict__ nidx,
    const float* __restrict__ kpts)
{
    __shared__ float  kp_s[KPN * 3];
    __shared__ float2 h2_s[8][KNNB][16];   // duplicated h (h,h), e padded to 16

    const int tid  = threadIdx.x;
    const int wid  = tid >> 5;
    const int lane = tid & 31;
    const int qid  = blockIdx.x * 8 + wid;   // grid = 6250 exact

    if (tid < KPN * 3) kp_s[tid] = kpts[tid];
    __syncthreads();

    // my neighbor (nb == lane)
    const int my_id = nidx[qid * KNNB + lane];
    const float qx = q_pts[qid * 3 + 0];
    const float qy = q_pts[qid * 3 + 1];
    const float qz = q_pts[qid * 3 + 2];

    float px, py, pz;
    if (my_id < M_S) {
        px = s_pts[my_id * 3 + 0];
        py = s_pts[my_id * 3 + 1];
        pz = s_pts[my_id * 3 + 2];
    } else { px = py = pz = 1e6f; }
    const float rx = px - qx, ry = py - qy, rz = pz - qz;

    #pragma unroll
    for (int e = 0; e < KPN; e++) {
        float dx = rx - kp_s[e * 3 + 0];
        float dy = ry - kp_s[e * 3 + 1];
        float dz = rz - kp_s[e * 3 + 2];
        float d2 = fmaf(dx, dx, fmaf(dy, dy, fmaf(dz, dz, 1e-8f)));
        float h  = fmaxf(1.0f - sqrtf(d2) * KP_EXT_INV, 0.0f);
        h2_s[wid][lane][e] = make_float2(h, h);
    }

    // validity count (reference: sum over channels > 0)
    bool flag = (my_id < M_S) && (g_rs[my_id] > 0.0f);
    unsigned bal = __ballot_sync(0xffffffffu, flag);
    __syncwarp();

    unsigned long long acc[KPN];
    #pragma unroll
    for (int e = 0; e < KPN; e++) acc[e] = 0ull;

    const float* sfp = s_feats;
    #pragma unroll 4
    for (int nb = 0; nb < KNNB; nb++) {
        int id = __shfl_sync(0xffffffffu, my_id, nb);
        float fx = 0.0f, fy = 0.0f;
        if (id < M_S) {
            float2 f = *(const float2*)&sfp[(size_t)id * CIN + lane * 2];
            fx = f.x; fy = f.y;
        }
        unsigned long long f2;
        asm("mov.b64 %0, {%1, %2};" : "=l"(f2) : "f"(fx), "f"(fy));
        #pragma unroll
        for (int e = 0; e < KPN; e++) {
            unsigned long long hv =
                *reinterpret_cast<const unsigned long long*>(&h2_s[wid][nb][e]);
            asm("fma.rn.f32x2 %0, %1, %2, %0;" : "+l"(acc[e]) : "l"(f2), "l"(hv));
        }
    }

    if (lane == 0) {
        int cnt = __popc(bal);
        g_inv[qid] = 1.0f / (float)(cnt > 0 ? cnt : 1);
    }

    // store tf32-rounded kernel_feats
    float* dst = &g_kf[(size_t)qid * KDIM + lane * 2];
    #pragma unroll
    for (int e = 0; e < KPN; e++) {
        float lo, hi;
        asm("mov.b64 {%0, %1}, %2;" : "=f"(lo), "=f"(hi) : "l"(acc[e]));
        uint2 st;
        asm("cvt.rna.tf32.f32 %0, %1;" : "=r"(st.x) : "f"(lo));
        asm("cvt.rna.tf32.f32 %0, %1;" : "=r"(st.y) : "f"(hi));
        *reinterpret_cast<uint2*>(&dst[e * CIN]) = st;
    }
}

// ---------------------------------------------------------------------------
// k2: tf32 tensor-core GEMM  C[50048,128] = A[50048,960] @ B[960,128],
// row-scaled by g_inv.  128x128x32 tiles, 2-stage cp.async pipeline,
// 8 warps (2x4), warp tile 64x32, mma.m16n8k8.tf32.
// ---------------------------------------------------------------------------
__device__ __forceinline__ void cpa16(float* dst, const float* src)
{
    unsigned sa = (unsigned)__cvta_generic_to_shared(dst);
    asm volatile("cp.async.cg.shared.global [%0], [%1], 16;\n" :: "r"(sa), "l"(src));
}

extern __shared__ float k2_smem[];

__global__ __launch_bounds__(256, 2) void k2_gemm(float* __restrict__ out)
{
    float* As = k2_smem;                 // 2 stages of BM x ASTR
    float* Bs = k2_smem + 2 * ASZ;       // 2 stages of BK x BSTR

    const int tid = threadIdx.x;
    const int wid = tid >> 5;
    const int lane = tid & 31;
    const int g = lane >> 2;             // 0..7
    const int t = lane & 3;              // 0..3
    const int warp_m = wid & 1;          // 0..1  (64 rows each)
    const int warp_n = wid >> 1;         // 0..3  (32 cols each)
    const int m0 = blockIdx.x * BM;

    const float* A = g_kf;
    const float* B = g_wt;

    float c[4][4][4];
    #pragma unroll
    for (int mt = 0; mt < 4; mt++)
        #pragma unroll
        for (int nt = 0; nt < 4; nt++)
            #pragma unroll
            for (int r = 0; r < 4; r++) c[mt][nt][r] = 0.0f;

    auto load_tiles = [&](int stage, int k0) {
        float* as = As + stage * ASZ;
        float* bs = Bs + stage * BSZ;
        #pragma unroll
        for (int it = 0; it < 4; it++) {
            int lin = tid + it * 256;            // 0..1023
            int row = lin >> 3, c4 = (lin & 7) * 4;
            cpa16(&as[row * ASTR + c4], &A[(size_t)(m0 + row) * KDIM + k0 + c4]);
        }
        #pragma unroll
        for (int it = 0; it < 4; it++) {
            int lin = tid + it * 256;
            int row = lin >> 5, c4 = (lin & 31) * 4;
            cpa16(&bs[row * BSTR + c4], &B[(k0 + row) * COUT + c4]);
        }
    };

    load_tiles(0, 0);
    asm volatile("cp.async.commit_group;");

    for (int kc = 0; kc < NKC; kc++) {
        if (kc + 1 < NKC) load_tiles((kc + 1) & 1, (kc + 1) * BK);
        asm volatile("cp.async.commit_group;");
        asm volatile("cp.async.wait_group 1;");
        __syncthreads();

        const float* as = As + (kc & 1) * ASZ;
        const float* bs = Bs + (kc & 1) * BSZ;

        #pragma unroll
        for (int kq = 0; kq < 4; kq++) {
            unsigned a_[4][4], b_[4][2];
            #pragma unroll
            for (int mt = 0; mt < 4; mt++) {
                const float* ap = as + (warp_m * 64 + mt * 16 + g) * ASTR + kq * 8 + t;
                a_[mt][0] = __float_as_uint(ap[0]);
                a_[mt][1] = __float_as_uint(ap[8 * ASTR]);
                a_[mt][2] = __float_as_uint(ap[4]);
                a_[mt][3] = __float_as_uint(ap[8 * ASTR + 4]);
            }
            #pragma unroll
            for (int nt = 0; nt < 4; nt++) {
                const float* bp = bs + (kq * 8 + t) * BSTR + warp_n * 32 + nt * 8 + g;
                b_[nt][0] = __float_as_uint(bp[0]);
                b_[nt][1] = __float_as_uint(bp[4 * BSTR]);
            }
            #pragma unroll
            for (int mt = 0; mt < 4; mt++)
                #pragma unroll
                for (int nt = 0; nt < 4; nt++)
                    asm volatile(
                        "mma.sync.aligned.m16n8k8.row.col.f32.tf32.tf32.f32 "
                        "{%0,%1,%2,%3}, {%4,%5,%6,%7}, {%8,%9}, {%0,%1,%2,%3};"
                        : "+f"(c[mt][nt][0]), "+f"(c[mt][nt][1]),
                          "+f"(c[mt][nt][2]), "+f"(c[mt][nt][3])
                        : "r"(a_[mt][0]), "r"(a_[mt][1]),
                          "r"(a_[mt][2]), "r"(a_[mt][3]),
                          "r"(b_[nt][0]), "r"(b_[nt][1]));
        }
        __syncthreads();
    }

    // epilogue: scale by g_inv, store
    #pragma unroll
    for (int mt = 0; mt < 4; mt++) {
        int r0 = m0 + warp_m * 64 + mt * 16 + g;
        int r1 = r0 + 8;
        float inv0 = g_inv[r0];       // padding rows read 0, never stored
        float inv1 = g_inv[r1];
        #pragma unroll
        for (int nt = 0; nt < 4; nt++) {
            int col = warp_n * 32 + nt * 8 + t * 2;
            if (r0 < N_Q) {
                float2 v = make_float2(c[mt][nt][0] * inv0, c[mt][nt][1] * inv0);
                *(float2*)&out[(size_t)r0 * COUT + col] = v;
            }
            if (r1 < N_Q) {
                float2 v = make_float2(c[mt][nt][2] * inv1, c[mt][nt][3] * inv1);
                *(float2*)&out[(size_t)r1 * COUT + col] = v;
            }
        }
    }
}

// ---------------------------------------------------------------------------
extern "C" void kernel_launch(void* const* d_in, const int* in_sizes, int n_in,
                              void* d_out, int out_size)
{
    const float* q_pts   = (const float*)d_in[0];
    const float* s_pts   = (const float*)d_in[1];
    const float* s_feats = (const float*)d_in[2];
    const int*   nidx    = (const int*)  d_in[3];
    const float* W       = (const float*)d_in[4];
    const float* kpts    = (const float*)d_in[5];
    float* out = (float*)d_out;

    const int k2smem = (2 * ASZ + 2 * BSZ) * (int)sizeof(float);  // 70656 B
    cudaFuncSetAttribute(k2_gemm, cudaFuncAttributeMaxDynamicSharedMemorySize, k2smem);

    k0a_rowsum<<<M_S / 8, 256>>>(s_feats);
    k0b_cvtw<<<(KDIM * COUT / 4) / 256, 256>>>(W);
    k1_gather<<<N_Q / 8, 256>>>(q_pts, s_pts, s_feats, nidx, kpts);
    k2_gemm<<<M_PAD / BM, 256, k2smem>>>(out);
}

// round 3
// speedup vs baseline: 4.7835x; 2.5314x over previous
#include <cuda_runtime.h>
#include <cuda_fp16.h>
#include <cstdint>

#define N_Q   50000
#define M_S   50000
#define KNNB  32
#define KPN   15
#define CIN   64
#define COUT  128
#define KDIM  (KPN * CIN)      // 960
#define KP_EXT_INV (1.0f / 1.2f)

#define BM    128
#define BK2   64               // k-chunk (halfs) for fp16 GEMM
#define NKC   (KDIM / BK2)     // 15
#define M_PAD (391 * BM)       // 50048

// Scratch (zero-initialized device globals)
__device__ __half g_kf16[(size_t)M_PAD * KDIM];   // fp16 kernel_feats (96 MB)
__device__ __half g_wt16[KDIM * COUT];            // fp16 weights
__device__ float  g_inv[M_PAD];
__device__ float  g_rs[M_S];                      // per-support-row channel sum

// ---------------------------------------------------------------------------
// k0a: rowsum of s_feats per support point (validity test)
// ---------------------------------------------------------------------------
__global__ __launch_bounds__(256) void k0a_rowsum(const float* __restrict__ sf)
{
    int wid = threadIdx.x >> 5, lane = threadIdx.x & 31;
    int row = blockIdx.x * 8 + wid;
    float2 v = *(const float2*)&sf[(size_t)row * CIN + lane * 2];
    float s = v.x + v.y;
    #pragma unroll
    for (int off = 16; off; off >>= 1) s += __shfl_xor_sync(0xffffffffu, s, off);
    if (lane == 0) g_rs[row] = s;
}

// ---------------------------------------------------------------------------
// k0b: W -> fp16
// ---------------------------------------------------------------------------
__global__ __launch_bounds__(256) void k0b_cvtw(const float* __restrict__ W)
{
    int i = (blockIdx.x * 256 + threadIdx.x) * 4;     // grid covers exactly
    float4 v = *(const float4*)&W[i];
    __half2 h0 = __floats2half2_rn(v.x, v.y);
    __half2 h1 = __floats2half2_rn(v.z, v.w);
    *reinterpret_cast<uint2*>(&g_wt16[i]) =
        make_uint2(*(unsigned*)&h0, *(unsigned*)&h1);
}

// ---------------------------------------------------------------------------
// k1: gather + sparse kernel-point aggregation.  Warp per query.
// lane = neighbor for geometry; lane = channel-pair for features.
// ---------------------------------------------------------------------------
#define NW1 4
__global__ __launch_bounds__(NW1 * 32) void k1_gather(
    const float* __restrict__ q_pts, const float* __restrict__ s_pts,
    const float* __restrict__ s_feats, const int* __restrict__ nidx,
    const float* __restrict__ kpts)
{
    __shared__ float  kp_s[KPN * 3];
    __shared__ float2 f_s[NW1][KNNB][32];    // gathered feats, 32 KB
    __shared__ float2 h2_s[NW1][KPN][KNNB];  // duplicated (h,h), 15 KB

    const int tid  = threadIdx.x;
    const int wid  = tid >> 5;
    const int lane = tid & 31;
    const int qid  = blockIdx.x * NW1 + wid;   // grid = 12500 exact

    if (tid < KPN * 3) kp_s[tid] = kpts[tid];
    __syncthreads();

    const int my_id = nidx[qid * KNNB + lane];

    // ---- stage neighbor features via cp.async (zero-fill shadow rows) ----
    {
        unsigned dst0 = (unsigned)__cvta_generic_to_shared(&f_s[wid][0][lane]);
        #pragma unroll 8
        for (int nb = 0; nb < KNNB; nb++) {
            int id = __shfl_sync(0xffffffffu, my_id, nb);
            int idc = id < M_S ? id : 0;
            int ssz = id < M_S ? 8 : 0;
            const float* src = &s_feats[(size_t)idc * CIN + lane * 2];
            asm volatile("cp.async.ca.shared.global [%0], [%1], 8, %2;\n"
                         :: "r"(dst0 + nb * 256), "l"(src), "r"(ssz));
        }
        asm volatile("cp.async.commit_group;");
    }

    // ---- geometry: lane = neighbor; compute h[e], per-e ballot masks ----
    const float qx = q_pts[qid * 3 + 0];
    const float qy = q_pts[qid * 3 + 1];
    const float qz = q_pts[qid * 3 + 2];
    float px, py, pz;
    if (my_id < M_S) {
        px = s_pts[my_id * 3 + 0];
        py = s_pts[my_id * 3 + 1];
        pz = s_pts[my_id * 3 + 2];
    } else { px = py = pz = 1e6f; }
    const float rx = px - qx, ry = py - qy, rz = pz - qz;

    unsigned emask[KPN];
    #pragma unroll
    for (int e = 0; e < KPN; e++) {
        float dx = rx - kp_s[e * 3 + 0];
        float dy = ry - kp_s[e * 3 + 1];
        float dz = rz - kp_s[e * 3 + 2];
        float d2 = fmaf(dx, dx, fmaf(dy, dy, fmaf(dz, dz, 1e-8f)));
        float h  = fmaxf(1.0f - sqrtf(d2) * KP_EXT_INV, 0.0f);
        h2_s[wid][e][lane] = make_float2(h, h);
        emask[e] = __ballot_sync(0xffffffffu, h > 0.0f);
    }

    // validity count
    bool flag = (my_id < M_S) && (g_rs[my_id < M_S ? my_id : 0] > 0.0f);
    unsigned bal = __ballot_sync(0xffffffffu, flag);
    if (lane == 0) {
        int cnt = __popc(bal);
        g_inv[qid] = 1.0f / (float)(cnt > 0 ? cnt : 1);
    }

    asm volatile("cp.async.wait_group 0;");
    __syncwarp();

    // ---- sparse aggregation: iterate only nonzero (e, nb) pairs ----
    __half* dst = &g_kf16[(size_t)qid * KDIM + lane * 2];
    #pragma unroll
    for (int e = 0; e < KPN; e++) {
        unsigned m = emask[e];          // warp-uniform
        if (m == 0) continue;           // column stays zero (static init)
        unsigned long long acc = 0ull;
        while (m) {
            int nb = __ffs(m) - 1;
            m &= m - 1;
            unsigned long long f2 =
                *reinterpret_cast<const unsigned long long*>(&f_s[wid][nb][lane]);
            unsigned long long hv =
                *reinterpret_cast<const unsigned long long*>(&h2_s[wid][e][nb]);
            asm("fma.rn.f32x2 %0, %1, %2, %0;" : "+l"(acc) : "l"(f2), "l"(hv));
        }
        float lo, hi;
        asm("mov.b64 {%0, %1}, %2;" : "=f"(lo), "=f"(hi) : "l"(acc));
        __half2 hv2 = __floats2half2_rn(lo, hi);
        *reinterpret_cast<__half2*>(&dst[e * CIN]) = hv2;
    }
}

// ---------------------------------------------------------------------------
// k2: fp16 tensor-core GEMM  C[50048,128] = A[50048,960] @ B[960,128],
// row-scaled by g_inv.  128x128x64 tiles, 2-stage cp.async, ldmatrix,
// XOR-swizzled smem, mma.m16n8k16.f16 with fp32 accumulate.
// ---------------------------------------------------------------------------
#define ASTAGE (BM * BK2)        // halfs per A stage (8192 = 16 KB)
#define BSTAGE (BK2 * COUT)      // halfs per B stage (8192 = 16 KB)

extern __shared__ __half k2_smem[];

__device__ __forceinline__ void cpa16s(unsigned dst, const __half* src)
{
    asm volatile("cp.async.cg.shared.global [%0], [%1], 16;\n" :: "r"(dst), "l"(src));
}

__global__ __launch_bounds__(256, 2) void k2_gemm(float* __restrict__ out)
{
    __half* As = k2_smem;
    __half* Bs = k2_smem + 2 * ASTAGE;
    const unsigned as_u = (unsigned)__cvta_generic_to_shared(As);
    const unsigned bs_u = (unsigned)__cvta_generic_to_shared(Bs);

    const int tid  = threadIdx.x;
    const int wid  = tid >> 5;
    const int lane = tid & 31;
    const int g = lane >> 2;          // 0..7
    const int t = lane & 3;           // 0..3
    const int warp_m = wid & 1;       // 64 rows each
    const int warp_n = wid >> 1;      // 32 cols each
    const int m0 = blockIdx.x * BM;

    const __half* A = g_kf16;
    const __half* B = g_wt16;

    float c[4][4][4];
    #pragma unroll
    for (int mt = 0; mt < 4; mt++)
        #pragma unroll
        for (int nt = 0; nt < 4; nt++)
            #pragma unroll
            for (int r = 0; r < 4; r++) c[mt][nt][r] = 0.0f;

    // tile loaders: 16B granules, XOR-swizzled (granule ^= row&7)
    auto load_tiles = [&](int stage, int k0) {
        unsigned as = as_u + stage * ASTAGE * 2;
        unsigned bs = bs_u + stage * BSTAGE * 2;
        #pragma unroll
        for (int it = 0; it < 4; it++) {
            int lin = tid + it * 256;            // 0..1023
            int row = lin >> 3, gr = lin & 7;
            int gsw = gr ^ (row & 7);
            cpa16s(as + (row * 8 + gsw) * 16,
                   &A[(size_t)(m0 + row) * KDIM + k0 + gr * 8]);
        }
        #pragma unroll
        for (int it = 0; it < 4; it++) {
            int lin = tid + it * 256;
            int row = lin >> 4, gr = lin & 15;
            int gsw = gr ^ (row & 7);            // flips low 3 bits only
            cpa16s(bs + (row * 16 + gsw) * 16,
                   &B[(k0 + row) * COUT + gr * 8]);
        }
    };

    load_tiles(0, 0);
    asm volatile("cp.async.commit_group;");

    for (int kc = 0; kc < NKC; kc++) {
        if (kc + 1 < NKC) load_tiles((kc + 1) & 1, (kc + 1) * BK2);
        asm volatile("cp.async.commit_group;");
        asm volatile("cp.async.wait_group 1;");
        __syncthreads();

        unsigned as = as_u + (kc & 1) * ASTAGE * 2;
        unsigned bs = bs_u + (kc & 1) * BSTAGE * 2;

        #pragma unroll
        for (int kq = 0; kq < 4; kq++) {        // 4 k16-steps per chunk
            unsigned a_[4][4], b_[4][2];
            // A fragments: 16x16 tiles, ldmatrix.x4
            #pragma unroll
            for (int mt = 0; mt < 4; mt++) {
                int row = warp_m * 64 + mt * 16 + (lane & 15);
                int gr  = kq * 2 + (lane >> 4);
                unsigned addr = as + (row * 8 + (gr ^ (row & 7))) * 16;
                asm volatile(
                    "ldmatrix.sync.aligned.m8n8.x4.shared.b16 {%0,%1,%2,%3}, [%4];"
                    : "=r"(a_[mt][0]), "=r"(a_[mt][1]),
                      "=r"(a_[mt][2]), "=r"(a_[mt][3]) : "r"(addr));
            }
            // B fragments: 16x16 (k x n) regions, ldmatrix.x4.trans -> 2 n-tiles
            #pragma unroll
            for (int cb = 0; cb < 2; cb++) {
                int row = kq * 16 + (lane & 15);
                int gr  = warp_n * 4 + cb * 2 + (lane >> 4);
                unsigned addr = bs + (row * 16 + (gr ^ (row & 7))) * 16;
                asm volatile(
                    "ldmatrix.sync.aligned.m8n8.x4.trans.shared.b16 {%0,%1,%2,%3}, [%4];"
                    : "=r"(b_[cb * 2][0]),     "=r"(b_[cb * 2][1]),
                      "=r"(b_[cb * 2 + 1][0]), "=r"(b_[cb * 2 + 1][1]) : "r"(addr));
            }
            #pragma unroll
            for (int mt = 0; mt < 4; mt++)
                #pragma unroll
                for (int nt = 0; nt < 4; nt++)
                    asm volatile(
                        "mma.sync.aligned.m16n8k16.row.col.f32.f16.f16.f32 "
                        "{%0,%1,%2,%3}, {%4,%5,%6,%7}, {%8,%9}, {%0,%1,%2,%3};"
                        : "+f"(c[mt][nt][0]), "+f"(c[mt][nt][1]),
                          "+f"(c[mt][nt][2]), "+f"(c[mt][nt][3])
                        : "r"(a_[mt][0]), "r"(a_[mt][1]),
                          "r"(a_[mt][2]), "r"(a_[mt][3]),
                          "r"(b_[nt][0]), "r"(b_[nt][1]));
        }
        __syncthreads();
    }

    // epilogue: scale by g_inv, store
    #pragma unroll
    for (int mt = 0; mt < 4; mt++) {
        int r0 = m0 + warp_m * 64 + mt * 16 + g;
        int r1 = r0 + 8;
        float inv0 = g_inv[r0];
        float inv1 = g_inv[r1];
        #pragma unroll
        for (int nt = 0; nt < 4; nt++) {
            int col = warp_n * 32 + nt * 8 + t * 2;
            if (r0 < N_Q)
                *(float2*)&out[(size_t)r0 * COUT + col] =
                    make_float2(c[mt][nt][0] * inv0, c[mt][nt][1] * inv0);
            if (r1 < N_Q)
                *(float2*)&out[(size_t)r1 * COUT + col] =
                    make_float2(c[mt][nt][2] * inv1, c[mt][nt][3] * inv1);
        }
    }
}

// ---------------------------------------------------------------------------
extern "C" void kernel_launch(void* const* d_in, const int* in_sizes, int n_in,
                              void* d_out, int out_size)
{
    const float* q_pts   = (const float*)d_in[0];
    const float* s_pts   = (const float*)d_in[1];
    const float* s_feats = (const float*)d_in[2];
    const int*   nidx    = (const int*)  d_in[3];
    const float* W       = (const float*)d_in[4];
    const float* kpts    = (const float*)d_in[5];
    float* out = (float*)d_out;

    const int k2smem = 2 * (ASTAGE + BSTAGE) * (int)sizeof(__half);  // 65536 B
    cudaFuncSetAttribute(k2_gemm, cudaFuncAttributeMaxDynamicSharedMemorySize, k2smem);

    k0a_rowsum<<<M_S / 8, 256>>>(s_feats);
    k0b_cvtw<<<(KDIM * COUT / 4) / 256, 256>>>(W);
    k1_gather<<<N_Q / NW1, NW1 * 32>>>(q_pts, s_pts, s_feats, nidx, kpts);
    k2_gemm<<<M_PAD / BM, 256, k2smem>>>(out);
}

// round 4
// speedup vs baseline: 4.8238x; 1.0084x over previous
#include <cuda_runtime.h>
#include <cuda_fp16.h>
#include <cstdint>

#define N_Q   50000
#define M_S   50000
#define KNNB  32
#define KPN   15
#define CIN   64
#define COUT  128
#define KDIM  (KPN * CIN)      // 960
#define KP_EXT_INV (1.0f / 1.2f)

#define BM    128
#define BK2   64               // k-chunk (halfs) for fp16 GEMM
#define NKC   (KDIM / BK2)     // 15
#define M_PAD (391 * BM)       // 50048

// Scratch (zero-initialized device globals)
__device__ __half g_kf16[(size_t)M_PAD * KDIM];   // fp16 kernel_feats
__device__ __half g_wt16[KDIM * COUT];            // fp16 weights
__device__ float  g_inv[M_PAD];
__device__ float  g_rs[M_S];                      // per-support-row channel sum

// ---------------------------------------------------------------------------
// k0a: rowsum of s_feats per support point (validity test)
// ---------------------------------------------------------------------------
__global__ __launch_bounds__(256) void k0a_rowsum(const float* __restrict__ sf)
{
    int wid = threadIdx.x >> 5, lane = threadIdx.x & 31;
    int row = blockIdx.x * 8 + wid;
    float2 v = *(const float2*)&sf[(size_t)row * CIN + lane * 2];
    float s = v.x + v.y;
    #pragma unroll
    for (int off = 16; off; off >>= 1) s += __shfl_xor_sync(0xffffffffu, s, off);
    if (lane == 0) g_rs[row] = s;
}

// ---------------------------------------------------------------------------
// k0b: W -> fp16
// ---------------------------------------------------------------------------
__global__ __launch_bounds__(256) void k0b_cvtw(const float* __restrict__ W)
{
    int i = (blockIdx.x * 256 + threadIdx.x) * 4;     // grid covers exactly
    float4 v = *(const float4*)&W[i];
    __half2 h0 = __floats2half2_rn(v.x, v.y);
    __half2 h1 = __floats2half2_rn(v.z, v.w);
    *reinterpret_cast<uint2*>(&g_wt16[i]) =
        make_uint2(*(unsigned*)&h0, *(unsigned*)&h1);
}

// ---------------------------------------------------------------------------
// k1: gather + sparse kernel-point aggregation.  Warp per query.
// Geometry builds a compact (h, nb) pair list per warp (grouped by kernel
// point e) via ballot-prefix; aggregation is flat counted loops — no ffs
// chains, no per-pair branches. Gather is gated on the "needed" mask.
// ---------------------------------------------------------------------------
#define NW1 4
__global__ __launch_bounds__(NW1 * 32) void k1_gather(
    const float* __restrict__ q_pts, const float* __restrict__ s_pts,
    const float* __restrict__ s_feats, const int* __restrict__ nidx,
    const float* __restrict__ kpts)
{
    __shared__ float  kp_s[KPN * 3];
    __shared__ float2 f_s[NW1][KNNB][32];           // gathered feats, 32 KB
    __shared__ float2 pair_s[NW1][KNNB * KPN];      // (h, nb) list, 15 KB

    const int tid  = threadIdx.x;
    const int wid  = tid >> 5;
    const int lane = tid & 31;
    const int qid  = blockIdx.x * NW1 + wid;        // grid = 12500 exact

    if (tid < KPN * 3) kp_s[tid] = kpts[tid];
    __syncthreads();

    const int my_id = nidx[qid * KNNB + lane];

    // ---- geometry: lane = neighbor; build pair list grouped by e ----
    const float qx = q_pts[qid * 3 + 0];
    const float qy = q_pts[qid * 3 + 1];
    const float qz = q_pts[qid * 3 + 2];
    float px, py, pz;
    if (my_id < M_S) {
        px = s_pts[my_id * 3 + 0];
        py = s_pts[my_id * 3 + 1];
        pz = s_pts[my_id * 3 + 2];
    } else { px = py = pz = 1e6f; }
    const float rx = px - qx, ry = py - qy, rz = pz - qz;

    float2* plist = pair_s[wid];
    const unsigned below = (1u << lane) - 1u;
    unsigned cnt[KPN];
    unsigned need = 0;
    int base = 0;
    #pragma unroll
    for (int e = 0; e < KPN; e++) {
        float dx = rx - kp_s[e * 3 + 0];
        float dy = ry - kp_s[e * 3 + 1];
        float dz = rz - kp_s[e * 3 + 2];
        float d2 = fmaf(dx, dx, fmaf(dy, dy, fmaf(dz, dz, 1e-8f)));
        float h  = 1.0f - sqrtf(d2) * KP_EXT_INV;
        unsigned m = __ballot_sync(0xffffffffu, h > 0.0f);
        if (m & (1u << lane)) {
            int pos = base + __popc(m & below);
            plist[pos] = make_float2(h, __int_as_float(lane));
        }
        cnt[e] = __popc(m);
        base += cnt[e];
        need |= m;
    }

    // ---- gated feature staging via cp.async (warp-uniform branches) ----
    {
        unsigned dst0 = (unsigned)__cvta_generic_to_shared(&f_s[wid][0][lane]);
        #pragma unroll
        for (int nb = 0; nb < KNNB; nb++) {
            if ((need >> nb) & 1u) {            // warp-uniform
                int id = __shfl_sync(0xffffffffu, my_id, nb);
                const float* src = &s_feats[(size_t)id * CIN + lane * 2];
                asm volatile("cp.async.ca.shared.global [%0], [%1], 8;\n"
                             :: "r"(dst0 + nb * 256), "l"(src));
            }
        }
        asm volatile("cp.async.commit_group;");
    }

    // ---- validity count ----
    int idc = my_id < M_S ? my_id : 0;
    bool flag = (my_id < M_S) && (g_rs[idc] > 0.0f);
    unsigned bal = __ballot_sync(0xffffffffu, flag);
    if (lane == 0) {
        int c2 = __popc(bal);
        g_inv[qid] = 1.0f / (float)(c2 > 0 ? c2 : 1);
    }

    asm volatile("cp.async.wait_group 0;");
    __syncwarp();

    // ---- aggregation: flat counted loops per kernel point ----
    const float2* fw = &f_s[wid][0][lane];
    __half* dst = &g_kf16[(size_t)qid * KDIM + lane * 2];
    int base2 = 0;
    #pragma unroll
    for (int e = 0; e < KPN; e++) {
        int c = cnt[e];
        if (c) {                                 // warp-uniform
            unsigned long long acc = 0ull;
            const float2* pp = plist + base2;
            #pragma unroll 2
            for (int i = 0; i < c; i++) {
                float2 p = pp[i];                // LDS.64 broadcast
                int nb = __float_as_int(p.y);
                unsigned long long hv, f2;
                asm("mov.b64 %0, {%1, %1};" : "=l"(hv) : "f"(p.x));
                f2 = *reinterpret_cast<const unsigned long long*>(&fw[nb * 32]);
                asm("fma.rn.f32x2 %0, %1, %2, %0;" : "+l"(acc) : "l"(f2), "l"(hv));
            }
            float lo, hi;
            asm("mov.b64 {%0, %1}, %2;" : "=f"(lo), "=f"(hi) : "l"(acc));
            *reinterpret_cast<__half2*>(&dst[e * CIN]) = __floats2half2_rn(lo, hi);
            base2 += c;
        }
    }
}

// ---------------------------------------------------------------------------
// k2: fp16 tensor-core GEMM  C[50048,128] = A[50048,960] @ B[960,128],
// row-scaled by g_inv.  128x128x64 tiles, 3-stage cp.async, ldmatrix,
// XOR-swizzled smem, mma.m16n8k16.f16 with fp32 accumulate.
// ---------------------------------------------------------------------------
#define ASTAGE (BM * BK2)        // halfs per A stage (16 KB)
#define BSTAGE (BK2 * COUT)      // halfs per B stage (16 KB)
#define NSTG   3

extern __shared__ __half k2_smem[];

__device__ __forceinline__ void cpa16s(unsigned dst, const __half* src)
{
    asm volatile("cp.async.cg.shared.global [%0], [%1], 16;\n" :: "r"(dst), "l"(src));
}

__global__ __launch_bounds__(256, 2) void k2_gemm(float* __restrict__ out)
{
    const unsigned as_u = (unsigned)__cvta_generic_to_shared(k2_smem);
    const unsigned bs_u = as_u + NSTG * ASTAGE * 2;

    const int tid  = threadIdx.x;
    const int wid  = tid >> 5;
    const int lane = tid & 31;
    const int g = lane >> 2;          // 0..7
    const int t = lane & 3;           // 0..3
    const int warp_m = wid & 1;       // 64 rows each
    const int warp_n = wid >> 1;      // 32 cols each
    const int m0 = blockIdx.x * BM;

    const __half* A = g_kf16;
    const __half* B = g_wt16;

    float c[4][4][4];
    #pragma unroll
    for (int mt = 0; mt < 4; mt++)
        #pragma unroll
        for (int nt = 0; nt < 4; nt++)
            #pragma unroll
            for (int r = 0; r < 4; r++) c[mt][nt][r] = 0.0f;

    auto load_tiles = [&](int stage, int k0) {
        unsigned as = as_u + stage * ASTAGE * 2;
        unsigned bs = bs_u + stage * BSTAGE * 2;
        #pragma unroll
        for (int it = 0; it < 4; it++) {
            int lin = tid + it * 256;            // 0..1023
            int row = lin >> 3, gr = lin & 7;
            int gsw = gr ^ (row & 7);
            cpa16s(as + (row * 8 + gsw) * 16,
                   &A[(size_t)(m0 + row) * KDIM + k0 + gr * 8]);
        }
        #pragma unroll
        for (int it = 0; it < 4; it++) {
            int lin = tid + it * 256;
            int row = lin >> 4, gr = lin & 15;
            int gsw = gr ^ (row & 7);
            cpa16s(bs + (row * 16 + gsw) * 16,
                   &B[(k0 + row) * COUT + gr * 8]);
        }
    };

    load_tiles(0, 0);
    asm volatile("cp.async.commit_group;");
    load_tiles(1, BK2);
    asm volatile("cp.async.commit_group;");

    int cs = 0;                 // compute stage
    int ls = 2;                 // next load stage
    for (int kc = 0; kc < NKC; kc++) {
        asm volatile("cp.async.wait_group 1;");
        __syncthreads();

        if (kc + 2 < NKC) {
            load_tiles(ls, (kc + 2) * BK2);
            ls = (ls == NSTG - 1) ? 0 : ls + 1;
        }
        asm volatile("cp.async.commit_group;");

        unsigned as = as_u + cs * ASTAGE * 2;
        unsigned bs = bs_u + cs * BSTAGE * 2;
        cs = (cs == NSTG - 1) ? 0 : cs + 1;

        #pragma unroll
        for (int kq = 0; kq < 4; kq++) {        // 4 k16-steps per chunk
            unsigned a_[4][4], b_[4][2];
            #pragma unroll
            for (int mt = 0; mt < 4; mt++) {
                int row = warp_m * 64 + mt * 16 + (lane & 15);
                int gr  = kq * 2 + (lane >> 4);
                unsigned addr = as + (row * 8 + (gr ^ (row & 7))) * 16;
                asm volatile(
                    "ldmatrix.sync.aligned.m8n8.x4.shared.b16 {%0,%1,%2,%3}, [%4];"
                    : "=r"(a_[mt][0]), "=r"(a_[mt][1]),
                      "=r"(a_[mt][2]), "=r"(a_[mt][3]) : "r"(addr));
            }
            #pragma unroll
            for (int cb = 0; cb < 2; cb++) {
                int row = kq * 16 + (lane & 15);
                int gr  = warp_n * 4 + cb * 2 + (lane >> 4);
                unsigned addr = bs + (row * 16 + (gr ^ (row & 7))) * 16;
                asm volatile(
                    "ldmatrix.sync.aligned.m8n8.x4.trans.shared.b16 {%0,%1,%2,%3}, [%4];"
                    : "=r"(b_[cb * 2][0]),     "=r"(b_[cb * 2][1]),
                      "=r"(b_[cb * 2 + 1][0]), "=r"(b_[cb * 2 + 1][1]) : "r"(addr));
            }
            #pragma unroll
            for (int mt = 0; mt < 4; mt++)
                #pragma unroll
                for (int nt = 0; nt < 4; nt++)
                    asm volatile(
                        "mma.sync.aligned.m16n8k16.row.col.f32.f16.f16.f32 "
                        "{%0,%1,%2,%3}, {%4,%5,%6,%7}, {%8,%9}, {%0,%1,%2,%3};"
                        : "+f"(c[mt][nt][0]), "+f"(c[mt][nt][1]),
                          "+f"(c[mt][nt][2]), "+f"(c[mt][nt][3])
                        : "r"(a_[mt][0]), "r"(a_[mt][1]),
                          "r"(a_[mt][2]), "r"(a_[mt][3]),
                          "r"(b_[nt][0]), "r"(b_[nt][1]));
        }
    }

    // epilogue: scale by g_inv, store
    #pragma unroll
    for (int mt = 0; mt < 4; mt++) {
        int r0 = m0 + warp_m * 64 + mt * 16 + g;
        int r1 = r0 + 8;
        float inv0 = g_inv[r0];
        float inv1 = g_inv[r1];
        #pragma unroll
        for (int nt = 0; nt < 4; nt++) {
            int col = warp_n * 32 + nt * 8 + t * 2;
            if (r0 < N_Q)
                *(float2*)&out[(size_t)r0 * COUT + col] =
                    make_float2(c[mt][nt][0] * inv0, c[mt][nt][1] * inv0);
            if (r1 < N_Q)
                *(float2*)&out[(size_t)r1 * COUT + col] =
                    make_float2(c[mt][nt][2] * inv1, c[mt][nt][3] * inv1);
        }
    }
}

// ---------------------------------------------------------------------------
extern "C" void kernel_launch(void* const* d_in, const int* in_sizes, int n_in,
                              void* d_out, int out_size)
{
    const float* q_pts   = (const float*)d_in[0];
    const float* s_pts   = (const float*)d_in[1];
    const float* s_feats = (const float*)d_in[2];
    const int*   nidx    = (const int*)  d_in[3];
    const float* W       = (const float*)d_in[4];
    const float* kpts    = (const float*)d_in[5];
    float* out = (float*)d_out;

    const int k2smem = NSTG * (ASTAGE + BSTAGE) * (int)sizeof(__half);  // 98304 B
    cudaFuncSetAttribute(k2_gemm, cudaFuncAttributeMaxDynamicSharedMemorySize, k2smem);

    k0a_rowsum<<<M_S / 8, 256>>>(s_feats);
    k0b_cvtw<<<(KDIM * COUT / 4) / 256, 256>>>(W);
    k1_gather<<<N_Q / NW1, NW1 * 32>>>(q_pts, s_pts, s_feats, nidx, kpts);
    k2_gemm<<<M_PAD / BM, 256, k2smem>>>(out);
}

// round 5
// speedup vs baseline: 6.8262x; 1.4151x over previous
#include <cuda_runtime.h>
#include <cuda_fp16.h>
#include <cstdint>

#define N_Q   50000
#define M_S   50000
#define KNNB  32
#define KPN   15
#define CIN   64
#define COUT  128
#define KDIM  (KPN * CIN)      // 960
#define KP_EXT_INV (1.0f / 1.2f)

#define BM    128
#define BK2   64               // k-chunk (halfs) for fp16 GEMM
#define NKC   (KDIM / BK2)     // 15
#define M_PAD (391 * BM)       // 50048

// Scratch (zero-initialized device globals)
__device__ __half g_kf16[(size_t)M_PAD * KDIM];   // fp16 kernel_feats
__device__ __half g_wt16[KDIM * COUT];            // fp16 weights
__device__ float  g_inv[M_PAD];
__device__ float  g_rs[M_S];                      // per-support-row channel sum

// ---------------------------------------------------------------------------
// k0a: rowsum of s_feats per support point (validity test)
// ---------------------------------------------------------------------------
__global__ __launch_bounds__(256) void k0a_rowsum(const float* __restrict__ sf)
{
    int wid = threadIdx.x >> 5, lane = threadIdx.x & 31;
    int row = blockIdx.x * 8 + wid;
    float2 v = *(const float2*)&sf[(size_t)row * CIN + lane * 2];
    float s = v.x + v.y;
    #pragma unroll
    for (int off = 16; off; off >>= 1) s += __shfl_xor_sync(0xffffffffu, s, off);
    if (lane == 0) g_rs[row] = s;
}

// ---------------------------------------------------------------------------
// k0b: W -> fp16
// ---------------------------------------------------------------------------
__global__ __launch_bounds__(256) void k0b_cvtw(const float* __restrict__ W)
{
    int i = (blockIdx.x * 256 + threadIdx.x) * 4;     // grid covers exactly
    float4 v = *(const float4*)&W[i];
    __half2 h0 = __floats2half2_rn(v.x, v.y);
    __half2 h1 = __floats2half2_rn(v.z, v.w);
    *reinterpret_cast<uint2*>(&g_wt16[i]) =
        make_uint2(*(unsigned*)&h0, *(unsigned*)&h1);
}

// ---------------------------------------------------------------------------
// k1: gather + sparse kernel-point aggregation.  Warp per query.
// Pair list stores (h, support_id); aggregation reads features directly via
// LDG (L1-cached across e-groups). No smem staging, no cp.async, branch-lean.
// ---------------------------------------------------------------------------
#define NW1 8
#define PLSZ (KNNB * KPN + 32)     // 480 pairs max + 32 dump slots
__global__ __launch_bounds__(NW1 * 32) void k1_gather(
    const float* __restrict__ q_pts, const float* __restrict__ s_pts,
    const float* __restrict__ s_feats, const int* __restrict__ nidx,
    const float* __restrict__ kpts)
{
    __shared__ float  kp_s[KPN * 3];
    __shared__ float2 pair_s[NW1][PLSZ];     // (h, id) list

    const int tid  = threadIdx.x;
    const int wid  = tid >> 5;
    const int lane = tid & 31;
    const int qid  = blockIdx.x * NW1 + wid;        // grid = 6250 exact

    if (tid < KPN * 3) kp_s[tid] = kpts[tid];
    __syncthreads();

    const int my_id = nidx[qid * KNNB + lane];

    // ---- geometry: lane = neighbor; build (h, id) pair list grouped by e ----
    const float qx = q_pts[qid * 3 + 0];
    const float qy = q_pts[qid * 3 + 1];
    const float qz = q_pts[qid * 3 + 2];
    float px, py, pz;
    if (my_id < M_S) {
        px = s_pts[my_id * 3 + 0];
        py = s_pts[my_id * 3 + 1];
        pz = s_pts[my_id * 3 + 2];
    } else { px = py = pz = 1e6f; }   // shadow: h always <= 0, never listed
    const float rx = px - qx, ry = py - qy, rz = pz - qz;

    float2* plist = pair_s[wid];
    const unsigned below = (1u << lane) - 1u;
    const float idf = __int_as_float(my_id);
    int cnt[KPN];
    int base = 0;
    #pragma unroll
    for (int e = 0; e < KPN; e++) {
        float dx = rx - kp_s[e * 3 + 0];
        float dy = ry - kp_s[e * 3 + 1];
        float dz = rz - kp_s[e * 3 + 2];
        float d2 = fmaf(dx, dx, fmaf(dy, dy, fmaf(dz, dz, 1e-8f)));
        float h  = 1.0f - sqrtf(d2) * KP_EXT_INV;
        unsigned m = __ballot_sync(0xffffffffu, h > 0.0f);
        // unconditional store: inactive lanes hit dump slots (SEL, no branch)
        int pos = (m & (1u << lane)) ? base + __popc(m & below)
                                     : KNNB * KPN + lane;
        plist[pos] = make_float2(h, idf);
        cnt[e] = __popc(m);
        base += cnt[e];
    }

    // ---- validity count ----
    int idc = my_id < M_S ? my_id : 0;
    bool flag = (my_id < M_S) && (g_rs[idc] > 0.0f);
    unsigned bal = __ballot_sync(0xffffffffu, flag);
    if (lane == 0) {
        int c2 = __popc(bal);
        g_inv[qid] = 1.0f / (float)(c2 > 0 ? c2 : 1);
    }
    __syncwarp();

    // ---- aggregation: lane = channel-pair; LDG features (L1-resident) ----
    const float* fb = s_feats + lane * 2;
    __half* dst = &g_kf16[(size_t)qid * KDIM + lane * 2];
    int base2 = 0;
    #pragma unroll
    for (int e = 0; e < KPN; e++) {
        int c = cnt[e];
        if (c) {                                 // warp-uniform
            unsigned long long acc = 0ull;
            const float2* pp = plist + base2;
            #pragma unroll 4
            for (int i = 0; i < c; i++) {
                float2 p = pp[i];                // LDS.64 broadcast
                int id = __float_as_int(p.y);
                unsigned long long hv, f2;
                asm("mov.b64 %0, {%1, %1};" : "=l"(hv) : "f"(p.x));
                f2 = *reinterpret_cast<const unsigned long long*>(
                         &fb[(size_t)id * CIN]);
                asm("fma.rn.f32x2 %0, %1, %2, %0;" : "+l"(acc) : "l"(f2), "l"(hv));
            }
            float lo, hi;
            asm("mov.b64 {%0, %1}, %2;" : "=f"(lo), "=f"(hi) : "l"(acc));
            *reinterpret_cast<__half2*>(&dst[e * CIN]) = __floats2half2_rn(lo, hi);
            base2 += c;
        }
    }
}

// ---------------------------------------------------------------------------
// k2: fp16 tensor-core GEMM  C[50048,128] = A[50048,960] @ B[960,128],
// row-scaled by g_inv.  128x128x64 tiles, 3-stage cp.async, ldmatrix,
// XOR-swizzled smem, mma.m16n8k16.f16 with fp32 accumulate.
// ---------------------------------------------------------------------------
#define ASTAGE (BM * BK2)        // halfs per A stage (16 KB)
#define BSTAGE (BK2 * COUT)      // halfs per B stage (16 KB)
#define NSTG   3

extern __shared__ __half k2_smem[];

__device__ __forceinline__ void cpa16s(unsigned dst, const __half* src)
{
    asm volatile("cp.async.cg.shared.global [%0], [%1], 16;\n" :: "r"(dst), "l"(src));
}

__global__ __launch_bounds__(256, 2) void k2_gemm(float* __restrict__ out)
{
    const unsigned as_u = (unsigned)__cvta_generic_to_shared(k2_smem);
    const unsigned bs_u = as_u + NSTG * ASTAGE * 2;

    const int tid  = threadIdx.x;
    const int wid  = tid >> 5;
    const int lane = tid & 31;
    const int g = lane >> 2;          // 0..7
    const int t = lane & 3;           // 0..3
    const int warp_m = wid & 1;       // 64 rows each
    const int warp_n = wid >> 1;      // 32 cols each
    const int m0 = blockIdx.x * BM;

    const __half* A = g_kf16;
    const __half* B = g_wt16;

    float c[4][4][4];
    #pragma unroll
    for (int mt = 0; mt < 4; mt++)
        #pragma unroll
        for (int nt = 0; nt < 4; nt++)
            #pragma unroll
            for (int r = 0; r < 4; r++) c[mt][nt][r] = 0.0f;

    auto load_tiles = [&](int stage, int k0) {
        unsigned as = as_u + stage * ASTAGE * 2;
        unsigned bs = bs_u + stage * BSTAGE * 2;
        #pragma unroll
        for (int it = 0; it < 4; it++) {
            int lin = tid + it * 256;            // 0..1023
            int row = lin >> 3, gr = lin & 7;
            int gsw = gr ^ (row & 7);
            cpa16s(as + (row * 8 + gsw) * 16,
                   &A[(size_t)(m0 + row) * KDIM + k0 + gr * 8]);
        }
        #pragma unroll
        for (int it = 0; it < 4; it++) {
            int lin = tid + it * 256;
            int row = lin >> 4, gr = lin & 15;
            int gsw = gr ^ (row & 7);
            cpa16s(bs + (row * 16 + gsw) * 16,
                   &B[(k0 + row) * COUT + gr * 8]);
        }
    };

    load_tiles(0, 0);
    asm volatile("cp.async.commit_group;");
    load_tiles(1, BK2);
    asm volatile("cp.async.commit_group;");

    int cs = 0;                 // compute stage
    int ls = 2;                 // next load stage
    for (int kc = 0; kc < NKC; kc++) {
        asm volatile("cp.async.wait_group 1;");
        __syncthreads();

        if (kc + 2 < NKC) {
            load_tiles(ls, (kc + 2) * BK2);
            ls = (ls == NSTG - 1) ? 0 : ls + 1;
        }
        asm volatile("cp.async.commit_group;");

        unsigned as = as_u + cs * ASTAGE * 2;
        unsigned bs = bs_u + cs * BSTAGE * 2;
        cs = (cs == NSTG - 1) ? 0 : cs + 1;

        #pragma unroll
        for (int kq = 0; kq < 4; kq++) {        // 4 k16-steps per chunk
            unsigned a_[4][4], b_[4][2];
            #pragma unroll
            for (int mt = 0; mt < 4; mt++) {
                int row = warp_m * 64 + mt * 16 + (lane & 15);
                int gr  = kq * 2 + (lane >> 4);
                unsigned addr = as + (row * 8 + (gr ^ (row & 7))) * 16;
                asm volatile(
                    "ldmatrix.sync.aligned.m8n8.x4.shared.b16 {%0,%1,%2,%3}, [%4];"
                    : "=r"(a_[mt][0]), "=r"(a_[mt][1]),
                      "=r"(a_[mt][2]), "=r"(a_[mt][3]) : "r"(addr));
            }
            #pragma unroll
            for (int cb = 0; cb < 2; cb++) {
                int row = kq * 16 + (lane & 15);
                int gr  = warp_n * 4 + cb * 2 + (lane >> 4);
                unsigned addr = bs + (row * 16 + (gr ^ (row & 7))) * 16;
                asm volatile(
                    "ldmatrix.sync.aligned.m8n8.x4.trans.shared.b16 {%0,%1,%2,%3}, [%4];"
                    : "=r"(b_[cb * 2][0]),     "=r"(b_[cb * 2][1]),
                      "=r"(b_[cb * 2 + 1][0]), "=r"(b_[cb * 2 + 1][1]) : "r"(addr));
            }
            #pragma unroll
            for (int mt = 0; mt < 4; mt++)
                #pragma unroll
                for (int nt = 0; nt < 4; nt++)
                    asm volatile(
                        "mma.sync.aligned.m16n8k16.row.col.f32.f16.f16.f32 "
                        "{%0,%1,%2,%3}, {%4,%5,%6,%7}, {%8,%9}, {%0,%1,%2,%3};"
                        : "+f"(c[mt][nt][0]), "+f"(c[mt][nt][1]),
                          "+f"(c[mt][nt][2]), "+f"(c[mt][nt][3])
                        : "r"(a_[mt][0]), "r"(a_[mt][1]),
                          "r"(a_[mt][2]), "r"(a_[mt][3]),
                          "r"(b_[nt][0]), "r"(b_[nt][1]));
        }
    }

    // epilogue: scale by g_inv, store
    #pragma unroll
    for (int mt = 0; mt < 4; mt++) {
        int r0 = m0 + warp_m * 64 + mt * 16 + g;
        int r1 = r0 + 8;
        float inv0 = g_inv[r0];
        float inv1 = g_inv[r1];
        #pragma unroll
        for (int nt = 0; nt < 4; nt++) {
            int col = warp_n * 32 + nt * 8 + t * 2;
            if (r0 < N_Q)
                *(float2*)&out[(size_t)r0 * COUT + col] =
                    make_float2(c[mt][nt][0] * inv0, c[mt][nt][1] * inv0);
            if (r1 < N_Q)
                *(float2*)&out[(size_t)r1 * COUT + col] =
                    make_float2(c[mt][nt][2] * inv1, c[mt][nt][3] * inv1);
        }
    }
}

// ---------------------------------------------------------------------------
extern "C" void kernel_launch(void* const* d_in, const int* in_sizes, int n_in,
                              void* d_out, int out_size)
{
    const float* q_pts   = (const float*)d_in[0];
    const float* s_pts   = (const float*)d_in[1];
    const float* s_feats = (const float*)d_in[2];
    const int*   nidx    = (const int*)  d_in[3];
    const float* W       = (const float*)d_in[4];
    const float* kpts    = (const float*)d_in[5];
    float* out = (float*)d_out;

    const int k2smem = NSTG * (ASTAGE + BSTAGE) * (int)sizeof(__half);  // 98304 B
    cudaFuncSetAttribute(k2_gemm, cudaFuncAttributeMaxDynamicSharedMemorySize, k2smem);

    k0a_rowsum<<<M_S / 8, 256>>>(s_feats);
    k0b_cvtw<<<(KDIM * COUT / 4) / 256, 256>>>(W);
    k1_gather<<<N_Q / NW1, NW1 * 32>>>(q_pts, s_pts, s_feats, nidx, kpts);
    k2_gemm<<<M_PAD / BM, 256, k2smem>>>(out);
}